// round 10
// baseline (speedup 1.0000x reference)
#include <cuda_runtime.h>

// ParallelBellowsLayers, fused single kernel, 256-bit (v8.b32) memory ops.
// out[b,c] = relu( sum_e relu(x[b,c]*w1[c,e]+b1[c,e]) * w2[c,e] + b2[c] ),
// C=40000, B=128, E=16. Output (B,2,20000) == (B,C) row-major -> elementwise.
//
// b1[c,:]==0 (this dataset) => sum_e relu(x*w1e)*w2e == x * (x>0 ? s_pos : s_neg).
//
// R1-R9 invariants: dur tracks per-thread memory-round count, nothing >31%
// busy, DRAM bytes == sizeof(x). This round halves rounds and total warps
// with 256-bit ld/st (legal evict_last vector form on sm_103: .v8.b32),
// fuses params into smem (one graph node), and splits rows 4x for occupancy.
// Channels with nonzero b1 / non-finite sums are NaN-flagged and take an
// exact per-element fallback (never taken on this dataset).

#define NGENES 20000
#define NTECH  2
#define CC     (NGENES * NTECH)    // 40000 channels
#define BB     128                 // batch rows
#define EE     16
#define NG8    (CC / 8)            // 5000 v8 channel-groups
#define GRP8B  32                  // v8-groups per block -> 256 channels/block
#define CHB    256                 // channels per block
#define NTHR   256
#define RSPLIT 4                   // row split across blockIdx.y
#define ROWSB  (BB / RSPLIT)       // 32 rows per block
#define RPS    (ROWSB / 8)         // 4 rows per thread (8 warp slices)

// ---- 256-bit global ops with inline L2::evict_last -------------------------
struct f8 { float v[8]; };

__device__ __forceinline__ f8 ldg8(const float* p)
{
    f8 r;
    unsigned u0,u1,u2,u3,u4,u5,u6,u7;
    asm volatile("ld.global.nc.L2::evict_last.v8.b32 {%0,%1,%2,%3,%4,%5,%6,%7}, [%8];"
                 : "=r"(u0),"=r"(u1),"=r"(u2),"=r"(u3),
                   "=r"(u4),"=r"(u5),"=r"(u6),"=r"(u7)
                 : "l"(p));
    r.v[0]=__uint_as_float(u0); r.v[1]=__uint_as_float(u1);
    r.v[2]=__uint_as_float(u2); r.v[3]=__uint_as_float(u3);
    r.v[4]=__uint_as_float(u4); r.v[5]=__uint_as_float(u5);
    r.v[6]=__uint_as_float(u6); r.v[7]=__uint_as_float(u7);
    return r;
}
__device__ __forceinline__ void stg8(float* p, const f8& r)
{
    asm volatile("st.global.L2::evict_last.v8.b32 [%0], {%1,%2,%3,%4,%5,%6,%7,%8};"
                 :: "l"(p),
                    "r"(__float_as_uint(r.v[0])), "r"(__float_as_uint(r.v[1])),
                    "r"(__float_as_uint(r.v[2])), "r"(__float_as_uint(r.v[3])),
                    "r"(__float_as_uint(r.v[4])), "r"(__float_as_uint(r.v[5])),
                    "r"(__float_as_uint(r.v[6])), "r"(__float_as_uint(r.v[7]))
                 : "memory");
}
// -----------------------------------------------------------------------------

// Exact per-element path for flagged channels (never taken on this dataset).
__device__ __noinline__ float bellows_exact(float xv, int c,
                                            const float* __restrict__ w1,
                                            const float* __restrict__ b1,
                                            const float* __restrict__ w2,
                                            float bias)
{
    float acc = 0.f;
    const float* w1r = w1 + (size_t)c * EE;
    const float* b1r = b1 + (size_t)c * EE;
    const float* w2r = w2 + (size_t)c * EE;
#pragma unroll 4
    for (int e = 0; e < EE; ++e) {
        float h = fmaxf(fmaf(xv, w1r[e], b1r[e]), 0.f);
        acc = fmaf(h, w2r[e], acc);
    }
    return fmaxf(acc + bias, 0.f);
}

__device__ __forceinline__ float bellows_fast(float xv, float sp, float sn, float bias)
{
    float s = (xv > 0.f) ? sp : sn;
    return fmaxf(fmaf(xv, s, bias), 0.f);
}

__global__ void __launch_bounds__(NTHR)
fused_kernel(const float* __restrict__ x,
             const float* __restrict__ w1,
             const float* __restrict__ b1,
             const float* __restrict__ w2,
             const float* __restrict__ b2,
             float* __restrict__ out)
{
    __shared__ float s_sp[CHB];
    __shared__ float s_sn[CHB];
    __shared__ float s_bf[CHB];

    const int tid = threadIdx.x;

    // ---- Phase 1: params for 256 channels, one thread per channel ----------
    {
        int c = blockIdx.x * CHB + tid;
        float sp = 0.f, sn = 0.f, bfv = 0.f;
        if (c < CC) {
            size_t off = (size_t)c * EE;
            f8 a0 = ldg8(w1 + off);
            f8 a1 = ldg8(w1 + off + 8);
            f8 z0 = ldg8(b1 + off);
            f8 z1 = ldg8(b1 + off + 8);
            f8 w0 = ldg8(w2 + off);
            f8 w1v = ldg8(w2 + off + 8);

            bool ok = true;
#pragma unroll
            for (int i = 0; i < 8; ++i) {
                ok = ok && (z0.v[i] == 0.f) && (z1.v[i] == 0.f);
                float p0 = a0.v[i] * w0.v[i];
                float p1 = a1.v[i] * w1v.v[i];
                sp += (a0.v[i] > 0.f) ? p0 : 0.f;
                sn += (a0.v[i] < 0.f) ? p0 : 0.f;
                sp += (a1.v[i] > 0.f) ? p1 : 0.f;
                sn += (a1.v[i] < 0.f) ? p1 : 0.f;
            }
            ok = ok && isfinite(sp) && isfinite(sn);
            if (!ok) sp = __int_as_float(0x7fc00000);   // NaN => exact fallback
            bfv = __ldg(b2 + c);
        }
        s_sp[tid] = sp;
        s_sn[tid] = sn;
        s_bf[tid] = bfv;
    }
    __syncthreads();

    // ---- Phase 2: streaming apply, 32B per thread per row ------------------
    const int grp8  = tid & 31;          // v8-group within block
    const int slice = tid >> 5;          // warp id -> row slice
    const int g8    = blockIdx.x * GRP8B + grp8;
    if (g8 >= NG8) return;
    const int c0   = g8 * 8;
    const int chl0 = grp8 * 8;

    float sp[8], sn[8], bf[8];
    bool any_fb = false;
#pragma unroll
    for (int i = 0; i < 8; ++i) {
        sp[i] = s_sp[chl0 + i];
        sn[i] = s_sn[chl0 + i];
        bf[i] = s_bf[chl0 + i];
        any_fb = any_fb || (sp[i] != sp[i]);
    }

    const int row0 = blockIdx.y * ROWSB + slice * RPS;
    const float* xp = x   + (size_t)row0 * CC + c0;
    float*       op = out + (size_t)row0 * CC + c0;

    if (!any_fb) {
        // depth-2 pipeline: load row r+1 while computing/storing row r
        f8 xa = ldg8(xp);
#pragma unroll
        for (int r = 0; r < RPS; ++r) {
            f8 xb;
            if (r + 1 < RPS) xb = ldg8(xp + (size_t)(r + 1) * CC);
            f8 o;
#pragma unroll
            for (int i = 0; i < 8; ++i)
                o.v[i] = bellows_fast(xa.v[i], sp[i], sn[i], bf[i]);
            stg8(op + (size_t)r * CC, o);
            xa = xb;
        }
    } else {
#pragma unroll 2
        for (int r = 0; r < RPS; ++r) {
            f8 xv = ldg8(xp + (size_t)r * CC);
            f8 o;
#pragma unroll
            for (int i = 0; i < 8; ++i) {
                o.v[i] = (sp[i] != sp[i])
                       ? bellows_exact(xv.v[i], c0 + i, w1, b1, w2, bf[i])
                       : bellows_fast(xv.v[i], sp[i], sn[i], bf[i]);
            }
            stg8(op + (size_t)r * CC, o);
        }
    }
}

extern "C" void kernel_launch(void* const* d_in, const int* in_sizes, int n_in,
                              void* d_out, int out_size)
{
    const float* x  = (const float*)d_in[0];   // (128, 40000)
    const float* w1 = (const float*)d_in[1];   // (40000, 16)
    const float* b1 = (const float*)d_in[2];   // (40000, 16)
    const float* w2 = (const float*)d_in[3];   // (40000, 16)
    const float* b2 = (const float*)d_in[4];   // (40000,)
    float* out = (float*)d_out;                // (128, 2, 20000) == (128, 40000)

    dim3 grid((NG8 + GRP8B - 1) / GRP8B, RSPLIT);  // (157, 4) = 628 blocks
    fused_kernel<<<grid, NTHR>>>(x, w1, b1, w2, b2, out);
}

// round 11
// speedup vs baseline: 1.3069x; 1.3069x over previous
#include <cuda_runtime.h>
#include <cstdint>

// ParallelBellowsLayers: per-channel 1->16->1 MLP with ReLU, C=40000, B=128, E=16.
// out[b,c] = relu( sum_e relu(x[b,c]*w1[c,e]+b1[c,e]) * w2[c,e] + b2[c] )
// Output (B,2,20000) == (B,C) row-major -> elementwise in x's layout.
// b1[c,:]==0 (this dataset) => sum_e relu(x*w1e)*w2e == x * (x>0 ? s_pos : s_neg).
//
// R1-R10 law: dur(apply) ~ cold-DRAM-bytes / 2.2-3 TB/s regardless of occupancy,
// MLP, vector width, cp.async -- with DRAM only ~28% busy. All variants made
// requests via warp-scheduled LDG. This version generates x's DRAM requests via
// the bulk-async engine (cp.async.bulk, UBLKCP): thread 0 of each CTA streams
// 2KB row-segments into a 4-stage smem ring with mbarrier expect_tx; compute
// threads consume their own 16B per row. Stores stay STG (writes are absorbed
// as dirty L2 lines -- measured free). Params from a small precompute kernel;
// NaN-flag routes nonzero-b1 / non-finite channels to an exact fallback
// (never taken on this dataset).

#define NGENES 20000
#define NTECH  2
#define CC     (NGENES * NTECH)    // 40000 channels
#define BB     128                 // batch rows
#define EE     16
#define CHUNK  512                 // channels per CTA
#define NCHUNK ((CC + CHUNK - 1) / CHUNK)   // 79 (last chunk = 64 channels)
#define RSPLIT 4                   // row split
#define ROWSB  (BB / RSPLIT)       // 32 rows per CTA
#define RPSTG  4                   // rows per stage
#define NSTAGE (ROWSB / RPSTG)     // 8 stages
#define DEPTH  4                   // ring depth (stages in flight)
#define SEGB   (CHUNK * 4)         // 2048 B per row segment (full chunk)
#define NTHR   128                 // one thread per 4 channels

// per-channel params {s_pos, s_neg, b2, flag(0 or NaN)}
__device__ float4 g_params[CC];

// ---- helpers ----------------------------------------------------------------
__device__ __forceinline__ uint32_t smem_u32(const void* p)
{
    uint32_t a;
    asm("{ .reg .u64 t; cvta.to.shared.u64 t, %1; cvt.u32.u64 %0, t; }"
        : "=r"(a) : "l"(p));
    return a;
}
__device__ __forceinline__ unsigned long long mk_policy()
{
    unsigned long long pol;
    asm volatile("createpolicy.fractional.L2::evict_last.b64 %0, 1.0;" : "=l"(pol));
    return pol;
}
__device__ __forceinline__ float4 ldg_el(const float* p, unsigned long long pol)
{
    float4 v;
    asm volatile("ld.global.nc.L2::cache_hint.v4.f32 {%0,%1,%2,%3}, [%4], %5;"
                 : "=f"(v.x), "=f"(v.y), "=f"(v.z), "=f"(v.w)
                 : "l"(p), "l"(pol));
    return v;
}
__device__ __forceinline__ void stg_el(float* p, float4 v, unsigned long long pol)
{
    asm volatile("st.global.L2::cache_hint.v4.f32 [%0], {%1,%2,%3,%4}, %5;"
                 :: "l"(p), "f"(v.x), "f"(v.y), "f"(v.z), "f"(v.w), "l"(pol)
                 : "memory");
}
__device__ __forceinline__ void mbar_init(uint32_t addr, uint32_t cnt)
{
    asm volatile("mbarrier.init.shared.b64 [%0], %1;" :: "r"(addr), "r"(cnt) : "memory");
}
__device__ __forceinline__ void mbar_expect_tx(uint32_t addr, uint32_t bytes)
{
    asm volatile("mbarrier.arrive.expect_tx.shared.b64 _, [%0], %1;"
                 :: "r"(addr), "r"(bytes) : "memory");
}
__device__ __forceinline__ void mbar_arrive(uint32_t addr)
{
    asm volatile("mbarrier.arrive.shared.b64 _, [%0];" :: "r"(addr) : "memory");
}
__device__ __forceinline__ void mbar_wait(uint32_t addr, int parity)
{
    asm volatile(
        "{\n\t.reg .pred P;\n\t"
        "W_%=:\n\t"
        "mbarrier.try_wait.parity.acquire.cta.shared::cta.b64 P, [%0], %1, 0x989680;\n\t"
        "@P bra.uni D_%=;\n\t"
        "bra.uni W_%=;\n\t"
        "D_%=:\n\t}"
        :: "r"(addr), "r"(parity) : "memory");
}
__device__ __forceinline__ void bulk_load(uint32_t dst_smem, const float* src,
                                          uint32_t bytes, uint32_t mbar)
{
    asm volatile("cp.async.bulk.shared::cta.global.mbarrier::complete_tx::bytes "
                 "[%0], [%1], %2, [%3];"
                 :: "r"(dst_smem), "l"(src), "r"(bytes), "r"(mbar) : "memory");
}
// -----------------------------------------------------------------------------

// Precompute: 4 threads per channel, shfl-reduced -> g_params AoS.
__global__ void __launch_bounds__(256)
precompute_kernel(const float* __restrict__ w1,
                  const float* __restrict__ b1,
                  const float* __restrict__ w2,
                  const float* __restrict__ b2)
{
    int t = blockIdx.x * 256 + threadIdx.x;
    int c = t >> 2;
    int part = t & 3;
    if (c >= CC) return;

    unsigned long long pol = mk_policy();
    size_t off = ((size_t)c * 4 + part) * 4;
    float4 a = ldg_el(w1 + off, pol);
    float4 z = ldg_el(b1 + off, pol);
    float4 w = ldg_el(w2 + off, pol);

    bool ok = (z.x == 0.f) && (z.y == 0.f) && (z.z == 0.f) && (z.w == 0.f);

    float sp = 0.f, sn = 0.f, p;
    p = a.x * w.x; sp += (a.x > 0.f) ? p : 0.f; sn += (a.x < 0.f) ? p : 0.f;
    p = a.y * w.y; sp += (a.y > 0.f) ? p : 0.f; sn += (a.y < 0.f) ? p : 0.f;
    p = a.z * w.z; sp += (a.z > 0.f) ? p : 0.f; sn += (a.z < 0.f) ? p : 0.f;
    p = a.w * w.w; sp += (a.w > 0.f) ? p : 0.f; sn += (a.w < 0.f) ? p : 0.f;

    float flag = ok ? 0.f : __int_as_float(0x7fc00000);

    sp += __shfl_xor_sync(0xffffffffu, sp, 1);
    sp += __shfl_xor_sync(0xffffffffu, sp, 2);
    sn += __shfl_xor_sync(0xffffffffu, sn, 1);
    sn += __shfl_xor_sync(0xffffffffu, sn, 2);
    flag += __shfl_xor_sync(0xffffffffu, flag, 1);   // NaN propagates
    flag += __shfl_xor_sync(0xffffffffu, flag, 2);

    if (part == 0) {
        if (!isfinite(sp) || !isfinite(sn)) flag = __int_as_float(0x7fc00000);
        g_params[c] = make_float4(sp, sn, __ldg(b2 + c), flag);
    }
}

// Exact per-element path for flagged channels (never taken on this dataset).
__device__ __noinline__ float bellows_exact(float xv, int c,
                                            const float* __restrict__ w1,
                                            const float* __restrict__ b1,
                                            const float* __restrict__ w2,
                                            float bias)
{
    float acc = 0.f;
    const float* w1r = w1 + (size_t)c * EE;
    const float* b1r = b1 + (size_t)c * EE;
    const float* w2r = w2 + (size_t)c * EE;
#pragma unroll 4
    for (int e = 0; e < EE; ++e) {
        float h = fmaxf(fmaf(xv, w1r[e], b1r[e]), 0.f);
        acc = fmaf(h, w2r[e], acc);
    }
    return fmaxf(acc + bias, 0.f);
}

__device__ __forceinline__ float bellows_fast(float xv, float sp, float sn, float bias)
{
    float s = (xv > 0.f) ? sp : sn;
    return fmaxf(fmaf(xv, s, bias), 0.f);
}

__global__ void __launch_bounds__(NTHR)
apply_kernel(const float* __restrict__ x,
             const float* __restrict__ w1,
             const float* __restrict__ b1,
             const float* __restrict__ w2,
             float* __restrict__ out)
{
    __shared__ __align__(16) unsigned char sbuf[DEPTH * RPSTG * SEGB];  // 32 KB
    __shared__ uint64_t mbar_mem[2 * DEPTH];   // full[0..3], empty[0..3]

    const int tid = threadIdx.x;
    const int c0 = blockIdx.x * CHUNK;
    const int count = min(CHUNK, CC - c0);          // 512 or 64 (last chunk)
    const uint32_t segbytes = (uint32_t)count * 4;  // per-row bytes
    const int row0 = blockIdx.y * ROWSB;

    const uint32_t sb = smem_u32(sbuf);
    const uint32_t mb = smem_u32(mbar_mem);
    // full[i] = mb + i*8 ; empty[i] = mb + 32 + i*8

    if (tid == 0) {
#pragma unroll
        for (int i = 0; i < DEPTH; ++i) {
            mbar_init(mb + i * 8, 1);           // producer arrive (expect_tx)
            mbar_init(mb + 32 + i * 8, NTHR);   // all consumers arrive
        }
    }
    __syncthreads();

    unsigned long long pol = mk_policy();

    // Per-thread params for its 4 channels (L2-warm: precompute just wrote them).
    const bool active = (tid * 4 < count);
    float4 p0, p1, p2, p3;
    bool any_fb = false;
    if (active) {
        const float* pp = reinterpret_cast<const float*>(g_params + c0 + tid * 4);
        p0 = ldg_el(pp + 0, pol);
        p1 = ldg_el(pp + 4, pol);
        p2 = ldg_el(pp + 8, pol);
        p3 = ldg_el(pp + 12, pol);
        any_fb = (p0.w != p0.w) || (p1.w != p1.w) || (p2.w != p2.w) || (p3.w != p3.w);
    }

    // Prologue: queue DEPTH stages (4 row-segments each).
    if (tid == 0) {
#pragma unroll
        for (int s = 0; s < DEPTH; ++s) {
            mbar_expect_tx(mb + s * 8, RPSTG * segbytes);
#pragma unroll
            for (int r = 0; r < RPSTG; ++r) {
                int row = row0 + s * RPSTG + r;
                bulk_load(sb + (uint32_t)(s * RPSTG + r) * SEGB,
                          x + (size_t)row * CC + c0, segbytes, mb + s * 8);
            }
        }
    }

    for (int s = 0; s < NSTAGE; ++s) {
        const int b = s & (DEPTH - 1);
        mbar_wait(mb + b * 8, (s >> 2) & 1);    // stage s data ready

        if (active) {
#pragma unroll
            for (int r = 0; r < RPSTG; ++r) {
                const float4 xv = *reinterpret_cast<const float4*>(
                    sbuf + (size_t)(b * RPSTG + r) * SEGB + (size_t)tid * 16);
                float4 o;
                if (!any_fb) {
                    o.x = bellows_fast(xv.x, p0.x, p0.y, p0.z);
                    o.y = bellows_fast(xv.y, p1.x, p1.y, p1.z);
                    o.z = bellows_fast(xv.z, p2.x, p2.y, p2.z);
                    o.w = bellows_fast(xv.w, p3.x, p3.y, p3.z);
                } else {
                    int cb = c0 + tid * 4;
                    o.x = (p0.w != p0.w) ? bellows_exact(xv.x, cb + 0, w1, b1, w2, p0.z)
                                         : bellows_fast(xv.x, p0.x, p0.y, p0.z);
                    o.y = (p1.w != p1.w) ? bellows_exact(xv.y, cb + 1, w1, b1, w2, p1.z)
                                         : bellows_fast(xv.y, p1.x, p1.y, p1.z);
                    o.z = (p2.w != p2.w) ? bellows_exact(xv.z, cb + 2, w1, b1, w2, p2.z)
                                         : bellows_fast(xv.z, p2.x, p2.y, p2.z);
                    o.w = (p3.w != p3.w) ? bellows_exact(xv.w, cb + 3, w1, b1, w2, p3.z)
                                         : bellows_fast(xv.w, p3.x, p3.y, p3.z);
                }
                int row = row0 + s * RPSTG + r;
                stg_el(out + (size_t)row * CC + c0 + tid * 4, o, pol);
            }
        }

        mbar_arrive(mb + 32 + b * 8);           // this thread done with stage s

        if (tid == 0 && s + DEPTH < NSTAGE) {
            // refill buffer b with stage s+DEPTH once ALL consumed stage s
            mbar_wait(mb + 32 + b * 8, (s >> 2) & 1);
            mbar_expect_tx(mb + b * 8, RPSTG * segbytes);
#pragma unroll
            for (int r = 0; r < RPSTG; ++r) {
                int row = row0 + (s + DEPTH) * RPSTG + r;
                bulk_load(sb + (uint32_t)(b * RPSTG + r) * SEGB,
                          x + (size_t)row * CC + c0, segbytes, mb + b * 8);
            }
        }
    }
}

extern "C" void kernel_launch(void* const* d_in, const int* in_sizes, int n_in,
                              void* d_out, int out_size)
{
    const float* x  = (const float*)d_in[0];   // (128, 40000)
    const float* w1 = (const float*)d_in[1];   // (40000, 16)
    const float* b1 = (const float*)d_in[2];   // (40000, 16)
    const float* w2 = (const float*)d_in[3];   // (40000, 16)
    const float* b2 = (const float*)d_in[4];   // (40000,)
    float* out = (float*)d_out;                // (128, 2, 20000) == (128, 40000)

    precompute_kernel<<<(CC * 4 + 255) / 256, 256>>>(w1, b1, w2, b2);

    dim3 grid(NCHUNK, RSPLIT);                 // (79, 4) = 316 CTAs
    apply_kernel<<<grid, NTHR>>>(x, w1, b1, w2, out);
}

// round 12
// speedup vs baseline: 1.5714x; 1.2024x over previous
#include <cuda_runtime.h>

// ParallelBellowsLayers: per-channel 1->16->1 MLP with ReLU, C=40000, B=128, E=16.
// out[b,c] = relu( sum_e relu(x[b,c]*w1[c,e]+b1[c,e]) * w2[c,e] + b2[c] )
// Output (B,2,20000) == (B,C) row-major -> elementwise in x's layout.
// b1[c,:]==0 (this dataset) => sum_e relu(x*w1e)*w2e == x * (x>0 ? s_pos : s_neg).
//
// R1-R11 conclusion: apply is pinned at ~9.4us by the mixed read+write DRAM
// stream (21MB in + 21MB out, path-independent: LDG == cp.async == TMA).
// The recoverable ~1.5us is the precompute node + inter-node serialization.
// This round overlaps them with Programmatic Dependent Launch:
//   precompute: griddepcontrol.launch_dependents after param stores
//   apply:      issue x loads -> griddepcontrol.wait -> load params
// NaN-flag in s_pos routes nonzero-b1 / non-finite channels to an exact
// per-element fallback (never taken on this dataset).

#define NGENES 20000
#define NTECH  2
#define CC     (NGENES * NTECH)   // 40000
#define BB     128
#define EE     16
#define NG     (CC / 4)           // 10000 float4 channel-groups
#define RROWS  4                  // batch rows per thread in apply

// SoA per-channel params (NaN in g_sp[c] => exact-fallback channel)
__device__ float g_sp[CC];
__device__ float g_sn[CC];
__device__ float g_bf[CC];

// ---- L2 evict_last cache-policy memory ops ---------------------------------
__device__ __forceinline__ unsigned long long mk_policy()
{
    unsigned long long pol;
    asm volatile("createpolicy.fractional.L2::evict_last.b64 %0, 1.0;" : "=l"(pol));
    return pol;
}
__device__ __forceinline__ float4 ldg_el(const float* p, unsigned long long pol)
{
    float4 v;
    asm volatile("ld.global.nc.L2::cache_hint.v4.f32 {%0,%1,%2,%3}, [%4], %5;"
                 : "=f"(v.x), "=f"(v.y), "=f"(v.z), "=f"(v.w)
                 : "l"(p), "l"(pol));
    return v;
}
__device__ __forceinline__ float ldg_el1(const float* p, unsigned long long pol)
{
    float v;
    asm volatile("ld.global.nc.L2::cache_hint.f32 %0, [%1], %2;"
                 : "=f"(v) : "l"(p), "l"(pol));
    return v;
}
__device__ __forceinline__ void stg_el(float* p, float4 v, unsigned long long pol)
{
    asm volatile("st.global.L2::cache_hint.v4.f32 [%0], {%1,%2,%3,%4}, %5;"
                 :: "l"(p), "f"(v.x), "f"(v.y), "f"(v.z), "f"(v.w), "l"(pol)
                 : "memory");
}
// -----------------------------------------------------------------------------

// Precompute: 4 threads per channel, shfl-reduced; signals dependents early.
__global__ void __launch_bounds__(256)
precompute_kernel(const float* __restrict__ w1,
                  const float* __restrict__ b1,
                  const float* __restrict__ w2,
                  const float* __restrict__ b2)
{
    int t = blockIdx.x * 256 + threadIdx.x;
    int c = t >> 2;
    int part = t & 3;
    if (c >= CC) return;   // exited threads satisfy launch_dependents

    unsigned long long pol = mk_policy();
    size_t off = ((size_t)c * 4 + part) * 4;
    float4 a = ldg_el(w1 + off, pol);
    float4 z = ldg_el(b1 + off, pol);
    float4 w = ldg_el(w2 + off, pol);

    bool ok = (z.x == 0.f) && (z.y == 0.f) && (z.z == 0.f) && (z.w == 0.f);

    float sp = 0.f, sn = 0.f, p;
    p = a.x * w.x; sp += (a.x > 0.f) ? p : 0.f; sn += (a.x < 0.f) ? p : 0.f;
    p = a.y * w.y; sp += (a.y > 0.f) ? p : 0.f; sn += (a.y < 0.f) ? p : 0.f;
    p = a.z * w.z; sp += (a.z > 0.f) ? p : 0.f; sn += (a.z < 0.f) ? p : 0.f;
    p = a.w * w.w; sp += (a.w > 0.f) ? p : 0.f; sn += (a.w < 0.f) ? p : 0.f;

    if (!ok) sp = __int_as_float(0x7fc00000);   // NaN survives the reduction

    sp += __shfl_xor_sync(0xffffffffu, sp, 1);
    sp += __shfl_xor_sync(0xffffffffu, sp, 2);
    sn += __shfl_xor_sync(0xffffffffu, sn, 1);
    sn += __shfl_xor_sync(0xffffffffu, sn, 2);

    if (part == 0) {
        if (!isfinite(sp) || !isfinite(sn)) sp = __int_as_float(0x7fc00000);
        g_sp[c] = sp;
        g_sn[c] = sn;
        g_bf[c] = ldg_el1(b2 + c, pol);
    }

    // Allow the dependent (apply) grid to launch now; its griddepcontrol.wait
    // still guarantees visibility of the param stores above.
    asm volatile("griddepcontrol.launch_dependents;");
}

// Exact per-element path for flagged channels (never taken on this dataset).
__device__ __noinline__ float bellows_exact(float xv, int c,
                                            const float* __restrict__ w1,
                                            const float* __restrict__ b1,
                                            const float* __restrict__ w2,
                                            float bias)
{
    float acc = 0.f;
    const float* w1r = w1 + (size_t)c * EE;
    const float* b1r = b1 + (size_t)c * EE;
    const float* w2r = w2 + (size_t)c * EE;
#pragma unroll 4
    for (int e = 0; e < EE; ++e) {
        float h = fmaxf(fmaf(xv, w1r[e], b1r[e]), 0.f);
        acc = fmaf(h, w2r[e], acc);
    }
    return fmaxf(acc + bias, 0.f);
}

__device__ __forceinline__ float bellows_fast(float xv, float sp, float sn, float bias)
{
    float s = (xv > 0.f) ? sp : sn;
    return fmaxf(fmaf(xv, s, bias), 0.f);
}

__global__ void __launch_bounds__(256)
apply_kernel(const float* __restrict__ x,
             const float* __restrict__ w1,
             const float* __restrict__ b1,
             const float* __restrict__ w2,
             float* __restrict__ out)
{
    int g = blockIdx.x * 256 + threadIdx.x;   // group of 4 channels
    if (g >= NG) return;
    int c  = g * 4;
    int b0 = blockIdx.y * RROWS;

    unsigned long long pol = mk_policy();

    const float* xp = x + (size_t)b0 * CC + c;
    float*       op = out + (size_t)b0 * CC + c;

    // x is independent of the precompute kernel: issue these loads BEFORE
    // griddepcontrol.wait so the predecessor's tail hides under them.
    float4 xv0 = ldg_el(xp, pol);
    float4 xv1 = ldg_el(xp + (size_t)1 * CC, pol);
    float4 xv2 = ldg_el(xp + (size_t)2 * CC, pol);
    float4 xv3 = ldg_el(xp + (size_t)3 * CC, pol);

    asm volatile("griddepcontrol.wait;" ::: "memory");

    float4 sp = ldg_el(g_sp + c, pol);
    float4 sn = ldg_el(g_sn + c, pol);
    float4 bf = ldg_el(g_bf + c, pol);

    bool any_fb = (sp.x != sp.x) || (sp.y != sp.y) || (sp.z != sp.z) || (sp.w != sp.w);

    if (!any_fb) {
        float4 o;
        o.x = bellows_fast(xv0.x, sp.x, sn.x, bf.x);
        o.y = bellows_fast(xv0.y, sp.y, sn.y, bf.y);
        o.z = bellows_fast(xv0.z, sp.z, sn.z, bf.z);
        o.w = bellows_fast(xv0.w, sp.w, sn.w, bf.w);
        stg_el(op, o, pol);
        o.x = bellows_fast(xv1.x, sp.x, sn.x, bf.x);
        o.y = bellows_fast(xv1.y, sp.y, sn.y, bf.y);
        o.z = bellows_fast(xv1.z, sp.z, sn.z, bf.z);
        o.w = bellows_fast(xv1.w, sp.w, sn.w, bf.w);
        stg_el(op + (size_t)1 * CC, o, pol);
        o.x = bellows_fast(xv2.x, sp.x, sn.x, bf.x);
        o.y = bellows_fast(xv2.y, sp.y, sn.y, bf.y);
        o.z = bellows_fast(xv2.z, sp.z, sn.z, bf.z);
        o.w = bellows_fast(xv2.w, sp.w, sn.w, bf.w);
        stg_el(op + (size_t)2 * CC, o, pol);
        o.x = bellows_fast(xv3.x, sp.x, sn.x, bf.x);
        o.y = bellows_fast(xv3.y, sp.y, sn.y, bf.y);
        o.z = bellows_fast(xv3.z, sp.z, sn.z, bf.z);
        o.w = bellows_fast(xv3.w, sp.w, sn.w, bf.w);
        stg_el(op + (size_t)3 * CC, o, pol);
    } else {
        float4 xs[RROWS] = {xv0, xv1, xv2, xv3};
#pragma unroll
        for (int r = 0; r < RROWS; ++r) {
            float4 xv = xs[r];
            float4 o;
            o.x = (sp.x != sp.x) ? bellows_exact(xv.x, c + 0, w1, b1, w2, bf.x)
                                 : bellows_fast(xv.x, sp.x, sn.x, bf.x);
            o.y = (sp.y != sp.y) ? bellows_exact(xv.y, c + 1, w1, b1, w2, bf.y)
                                 : bellows_fast(xv.y, sp.y, sn.y, bf.y);
            o.z = (sp.z != sp.z) ? bellows_exact(xv.z, c + 2, w1, b1, w2, bf.z)
                                 : bellows_fast(xv.z, sp.z, sn.z, bf.z);
            o.w = (sp.w != sp.w) ? bellows_exact(xv.w, c + 3, w1, b1, w2, bf.w)
                                 : bellows_fast(xv.w, sp.w, sn.w, bf.w);
            stg_el(op + (size_t)r * CC, o, pol);
        }
    }
}

extern "C" void kernel_launch(void* const* d_in, const int* in_sizes, int n_in,
                              void* d_out, int out_size)
{
    const float* x  = (const float*)d_in[0];   // (128, 40000)
    const float* w1 = (const float*)d_in[1];   // (40000, 16)
    const float* b1 = (const float*)d_in[2];   // (40000, 16)
    const float* w2 = (const float*)d_in[3];   // (40000, 16)
    const float* b2 = (const float*)d_in[4];   // (40000,)
    float* out = (float*)d_out;                // (128, 2, 20000) == (128, 40000)

    precompute_kernel<<<(CC * 4 + 255) / 256, 256>>>(w1, b1, w2, b2);

    // apply: launched with Programmatic Stream Serialization so it can begin
    // while precompute drains; griddepcontrol.wait provides the ordering.
    cudaLaunchConfig_t cfg = {};
    cfg.gridDim  = dim3((NG + 255) / 256, BB / RROWS);   // (40, 32) = 1280 blocks
    cfg.blockDim = dim3(256, 1, 1);
    cfg.dynamicSmemBytes = 0;
    cfg.stream = 0;   // same (capture) stream as the precompute launch

    cudaLaunchAttribute attrs[1];
    attrs[0].id = cudaLaunchAttributeProgrammaticStreamSerialization;
    attrs[0].val.programmaticStreamSerializationAllowed = 1;
    cfg.attrs = attrs;
    cfg.numAttrs = 1;

    cudaLaunchKernelEx(&cfg, apply_kernel, x, w1, b1, w2, out);
}